// round 3
// baseline (speedup 1.0000x reference)
#include <cuda_runtime.h>
#include <cstddef>

#define GRID3 256
#define NVOX  (256*256*256)
#define HT    16    // h rows per CTA in fused HD pass
#define DSEG  32    // d slices per CTA

// Static device scratch (allowed; no allocation)
__device__ float g_vol[NVOX];

// ---------------------------------------------------------------------------
// Scatter with fused W-blur: each point atomically adds f to the 5 voxels
// (d, h, w-2..w+2), clipped to the volume. After this pass g_vol holds the
// W-blurred densified volume.
// ---------------------------------------------------------------------------
__global__ void scatter_w_kernel(const float* __restrict__ feats,
                                 const int* __restrict__ coords,
                                 int n)
{
    int i = blockIdx.x * blockDim.x + threadIdx.x;
    if (i >= n) return;
    float f = feats[i];
    int d = coords[3 * i + 0];
    int h = coords[3 * i + 1];
    int w = coords[3 * i + 2];
    float* base = g_vol + (((size_t)d << 16) | ((size_t)h << 8));
#pragma unroll
    for (int dw = -2; dw <= 2; dw++) {
        int ww = w + dw;
        if (ww >= 0 && ww < GRID3) atomicAdd(base + ww, f);
    }
}

// ---------------------------------------------------------------------------
// Fused H+D box blur, no shared memory. Thread = one w column within an
// (h-tile, d-segment) CTA. Marches d; per slice loads HT+4 W-blurred values
// (coalesced across w), computes HT H-sums via a register sliding window,
// and keeps a 4-deep depth-ring per h row: out(d) = ring sum + new H-sum.
// ---------------------------------------------------------------------------
__global__ __launch_bounds__(256) void blur_hd_kernel(const float* __restrict__ in,
                                                      float* __restrict__ out)
{
    int w  = threadIdx.x;               // 0..255
    int h0 = blockIdx.x * HT;           // 0,16,...,240
    int d0 = blockIdx.y * DSEG;         // 0,32,...,224

    float ring[HT][4];
#pragma unroll
    for (int i = 0; i < HT; i++) {
#pragma unroll
        for (int k = 0; k < 4; k++) ring[i][k] = 0.f;
    }

    for (int s = d0 - 2; s < d0 + DSEG + 2; s++) {
        // Load the 20 h-rows (with halo) of W-blurred slice s at column w.
        float v[HT + 4];
        if (s >= 0 && s < GRID3) {
            const float* slice = in + ((size_t)s << 16) + (size_t)w;
#pragma unroll
            for (int r = 0; r < HT + 4; r++) {
                int h = h0 - 2 + r;
                v[r] = (h >= 0 && h < GRID3) ? slice[(size_t)h << 8] : 0.f;
            }
        } else {
#pragma unroll
            for (int r = 0; r < HT + 4; r++) v[r] = 0.f;
        }

        int d = s - 2;                  // output slice completed this step
        bool emit = (d >= d0);          // skip warmup steps
#pragma unroll
        for (int i = 0; i < HT; i++) {
            float hs  = ((v[i] + v[i + 1]) + (v[i + 2] + v[i + 3])) + v[i + 4];
            float sum = ((ring[i][0] + ring[i][1]) + (ring[i][2] + ring[i][3])) + hs;
            if (emit)
                out[((size_t)d << 16) + ((size_t)(h0 + i) << 8) + (size_t)w] = sum;
            ring[i][0] = ring[i][1];
            ring[i][1] = ring[i][2];
            ring[i][2] = ring[i][3];
            ring[i][3] = hs;
        }
    }
}

// ---------------------------------------------------------------------------
// Launch: memset vol -> scatter+W (->vol) -> fused HD (vol -> d_out)
// All default-stream, graph-capturable, allocation-free.
// ---------------------------------------------------------------------------
extern "C" void kernel_launch(void* const* d_in, const int* in_sizes, int n_in,
                              void* d_out, int out_size)
{
    const float* feats  = (const float*)d_in[0];
    const int*   coords = (const int*)d_in[1];
    int n = in_sizes[0];
    float* out = (float*)d_out;

    float* vol = nullptr;
    cudaGetSymbolAddress((void**)&vol, g_vol);

    cudaMemsetAsync(vol, 0, (size_t)NVOX * sizeof(float));

    scatter_w_kernel<<<(n + 255) / 256, 256>>>(feats, coords, n);

    dim3 gridHD(GRID3 / HT, GRID3 / DSEG);
    blur_hd_kernel<<<gridHD, GRID3>>>(vol, out);
}

// round 6
// speedup vs baseline: 1.2240x; 1.2240x over previous
#include <cuda_runtime.h>
#include <cstddef>

#define GRID3 256
#define NVOX  (256*256*256)
#define HT    8     // h rows per thread in fused HD pass
#define DSEG  16    // d slices per CTA

// Static device scratch (allowed; no allocation)
__device__ float g_vol[NVOX];

// ---------------------------------------------------------------------------
// Scatter with fused W-blur: each point atomically adds f to the 5 voxels
// (d, h, w-2..w+2), clipped to the volume. After this pass g_vol holds the
// W-blurred densified volume.
// ---------------------------------------------------------------------------
__global__ void scatter_w_kernel(const float* __restrict__ feats,
                                 const int* __restrict__ coords,
                                 int n)
{
    int i = blockIdx.x * blockDim.x + threadIdx.x;
    if (i >= n) return;
    float f = feats[i];
    int d = coords[3 * i + 0];
    int h = coords[3 * i + 1];
    int w = coords[3 * i + 2];
    float* base = g_vol + (((size_t)d << 16) | ((size_t)h << 8));
#pragma unroll
    for (int dw = -2; dw <= 2; dw++) {
        int ww = w + dw;
        if (ww >= 0 && ww < GRID3) atomicAdd(base + ww, f);
    }
}

// ---------------------------------------------------------------------------
// Fused H+D box blur, no shared memory. Thread = one w column within an
// (h-tile, d-segment) CTA. Marches d; per slice loads HT+4 W-blurred values
// (coalesced across w), computes HT H-sums via a register sliding window,
// and keeps a 4-deep depth-ring per h row: out(d) = ring sum + new H-sum.
// Tiled small (HT=8, DSEG=16) for 512 CTAs / high occupancy.
// ---------------------------------------------------------------------------
__global__ __launch_bounds__(256) void blur_hd_kernel(const float* __restrict__ in,
                                                      float* __restrict__ out)
{
    int w  = threadIdx.x;               // 0..255
    int h0 = blockIdx.x * HT;           // 32 tiles
    int d0 = blockIdx.y * DSEG;         // 16 segments

    float ring[HT][4];
#pragma unroll
    for (int i = 0; i < HT; i++) {
#pragma unroll
        for (int k = 0; k < 4; k++) ring[i][k] = 0.f;
    }

    for (int s = d0 - 2; s < d0 + DSEG + 2; s++) {
        // Load the HT+4 h-rows (with halo) of W-blurred slice s at column w.
        float v[HT + 4];
        if (s >= 0 && s < GRID3) {
            const float* slice = in + ((size_t)s << 16) + (size_t)w;
#pragma unroll
            for (int r = 0; r < HT + 4; r++) {
                int h = h0 - 2 + r;
                v[r] = (h >= 0 && h < GRID3) ? slice[(size_t)h << 8] : 0.f;
            }
        } else {
#pragma unroll
            for (int r = 0; r < HT + 4; r++) v[r] = 0.f;
        }

        int d = s - 2;                  // output slice completed this step
        bool emit = (d >= d0);          // skip warmup steps
#pragma unroll
        for (int i = 0; i < HT; i++) {
            float hs  = ((v[i] + v[i + 1]) + (v[i + 2] + v[i + 3])) + v[i + 4];
            float sum = ((ring[i][0] + ring[i][1]) + (ring[i][2] + ring[i][3])) + hs;
            if (emit)
                out[((size_t)d << 16) + ((size_t)(h0 + i) << 8) + (size_t)w] = sum;
            ring[i][0] = ring[i][1];
            ring[i][1] = ring[i][2];
            ring[i][2] = ring[i][3];
            ring[i][3] = hs;
        }
    }
}

// ---------------------------------------------------------------------------
// Launch: memset vol -> scatter+W (->vol) -> fused HD (vol -> d_out)
// All default-stream, graph-capturable, allocation-free.
// ---------------------------------------------------------------------------
extern "C" void kernel_launch(void* const* d_in, const int* in_sizes, int n_in,
                              void* d_out, int out_size)
{
    const float* feats  = (const float*)d_in[0];
    const int*   coords = (const int*)d_in[1];
    int n = in_sizes[0];
    float* out = (float*)d_out;

    float* vol = nullptr;
    cudaGetSymbolAddress((void**)&vol, g_vol);

    cudaMemsetAsync(vol, 0, (size_t)NVOX * sizeof(float));

    scatter_w_kernel<<<(n + 255) / 256, 256>>>(feats, coords, n);

    dim3 gridHD(GRID3 / HT, GRID3 / DSEG);
    blur_hd_kernel<<<gridHD, GRID3>>>(vol, out);
}

// round 7
// speedup vs baseline: 1.5178x; 1.2401x over previous
#include <cuda_runtime.h>
#include <cstddef>

#define GRID3 256
#define NVOX  (256*256*256)
#define HT    8     // h rows per thread in fused HD pass
#define DSEG  16    // d slices per CTA

// Static device scratch (allowed; no allocation)
__device__ float g_vol[NVOX];

// ---------------------------------------------------------------------------
// Scatter with fused W-blur: each point adds f to voxels (d,h,w-2..w+2).
// Implemented as two 16B-aligned vector reductions (red.global.add.v4.f32)
// over the aligned 8-float window containing the 5-tap span; lanes outside
// the span contribute +0.0 (value-neutral).
// ---------------------------------------------------------------------------
__global__ void scatter_w_kernel(const float* __restrict__ feats,
                                 const int* __restrict__ coords,
                                 int n)
{
    int i = blockIdx.x * blockDim.x + threadIdx.x;
    if (i >= n) return;
    float f = feats[i];
    int d = coords[3 * i + 0];
    int h = coords[3 * i + 1];
    int w = coords[3 * i + 2];

    int base = (w - 2) & ~3;                 // 16B-aligned quad start
    base = base < 0 ? 0 : (base > GRID3 - 8 ? GRID3 - 8 : base);

    float* p = g_vol + (((size_t)d << 16) | ((size_t)h << 8)) + base;

    float vals[8];
#pragma unroll
    for (int j = 0; j < 8; j++) {
        int idx = base + j;
        vals[j] = (idx >= w - 2 && idx <= w + 2) ? f : 0.f;
    }
    asm volatile("red.global.add.v4.f32 [%0], {%1,%2,%3,%4};"
                 :: "l"(p), "f"(vals[0]), "f"(vals[1]), "f"(vals[2]), "f"(vals[3])
                 : "memory");
    asm volatile("red.global.add.v4.f32 [%0], {%1,%2,%3,%4};"
                 :: "l"(p + 4), "f"(vals[4]), "f"(vals[5]), "f"(vals[6]), "f"(vals[7])
                 : "memory");
}

// ---------------------------------------------------------------------------
// Load one d-slice's column of HT+4 h-rows (zero outside volume) and produce
// the HT 5-tap H-sums via an incremental sliding window.
// ---------------------------------------------------------------------------
__device__ __forceinline__ void load_hs(const float* __restrict__ in,
                                        int s, int h0, int w, float* hs)
{
    float v[HT + 4];
    if (s >= 0 && s < GRID3) {
        const float* slice = in + ((size_t)s << 16) + (size_t)w;
#pragma unroll
        for (int r = 0; r < HT + 4; r++) {
            int h = h0 - 2 + r;
            v[r] = (h >= 0 && h < GRID3) ? slice[(size_t)h << 8] : 0.f;
        }
    } else {
#pragma unroll
        for (int r = 0; r < HT + 4; r++) v[r] = 0.f;
    }
    hs[0] = ((v[0] + v[1]) + (v[2] + v[3])) + v[4];
#pragma unroll
    for (int i = 1; i < HT; i++)
        hs[i] = hs[i - 1] + (v[i + 4] - v[i - 1]);
}

// ---------------------------------------------------------------------------
// Fused H+D box blur, no shared memory. Thread = one w column within an
// (h-tile, d-segment) CTA. Peeled 4-slice warmup fills a 4-deep depth ring
// of H-sums; the fully-unrolled steady loop rotates the ring statically
// (no MOVs) and emits one output slice per step.
// ---------------------------------------------------------------------------
__global__ __launch_bounds__(256) void blur_hd_kernel(const float* __restrict__ in,
                                                      float* __restrict__ out)
{
    int w  = threadIdx.x;               // 0..255
    int h0 = blockIdx.x * HT;           // 32 tiles
    int d0 = blockIdx.y * DSEG;         // 16 segments

    float ring[4][HT];

    // Warmup: slices d0-2 .. d0+1
#pragma unroll
    for (int k = 0; k < 4; k++)
        load_hs(in, d0 - 2 + k, h0, w, ring[k]);

    // Steady: each step t loads slice d0+2+t and emits output slice d0+t.
#pragma unroll
    for (int t = 0; t < DSEG; t++) {
        float hs[HT];
        load_hs(in, d0 + 2 + t, h0, w, hs);
        float* o = out + ((size_t)(d0 + t) << 16) + ((size_t)h0 << 8) + (size_t)w;
#pragma unroll
        for (int i = 0; i < HT; i++) {
            o[(size_t)i << 8] =
                ((ring[0][i] + ring[1][i]) + (ring[2][i] + ring[3][i])) + hs[i];
            ring[t & 3][i] = hs[i];     // static after unroll: register rotation
        }
    }
}

// ---------------------------------------------------------------------------
// Launch: memset vol -> scatter+W (->vol) -> fused HD (vol -> d_out)
// All default-stream, graph-capturable, allocation-free.
// ---------------------------------------------------------------------------
extern "C" void kernel_launch(void* const* d_in, const int* in_sizes, int n_in,
                              void* d_out, int out_size)
{
    const float* feats  = (const float*)d_in[0];
    const int*   coords = (const int*)d_in[1];
    int n = in_sizes[0];
    float* out = (float*)d_out;

    float* vol = nullptr;
    cudaGetSymbolAddress((void**)&vol, g_vol);

    cudaMemsetAsync(vol, 0, (size_t)NVOX * sizeof(float));

    scatter_w_kernel<<<(n + 255) / 256, 256>>>(feats, coords, n);

    dim3 gridHD(GRID3 / HT, GRID3 / DSEG);
    blur_hd_kernel<<<gridHD, GRID3>>>(vol, out);
}

// round 12
// speedup vs baseline: 1.5312x; 1.0088x over previous
#include <cuda_runtime.h>
#include <cstddef>

#define GRID3 256
#define NVOX  (256*256*256)
#define HT    8     // h rows per thread in fused HD pass
#define DSEG  8     // d slices per CTA -> 1024 CTAs

// Static device scratch (allowed; no allocation)
__device__ float g_vol[NVOX];

// ---------------------------------------------------------------------------
// Scatter with fused W-blur: each point adds f to voxels (d,h,w-2..w+2).
// Two 16B-aligned vector reductions over the aligned 8-float window
// containing the 5-tap span; lanes outside the span add +0.0.
// ---------------------------------------------------------------------------
__global__ void scatter_w_kernel(const float* __restrict__ feats,
                                 const int* __restrict__ coords,
                                 int n)
{
    int i = blockIdx.x * blockDim.x + threadIdx.x;
    if (i >= n) return;
    float f = feats[i];
    int d = coords[3 * i + 0];
    int h = coords[3 * i + 1];
    int w = coords[3 * i + 2];

    int base = (w - 2) & ~3;                 // 16B-aligned quad start
    base = base < 0 ? 0 : (base > GRID3 - 8 ? GRID3 - 8 : base);

    float* p = g_vol + (((size_t)d << 16) | ((size_t)h << 8)) + base;

    float vals[8];
#pragma unroll
    for (int j = 0; j < 8; j++) {
        int idx = base + j;
        vals[j] = (idx >= w - 2 && idx <= w + 2) ? f : 0.f;
    }
    asm volatile("red.global.add.v4.f32 [%0], {%1,%2,%3,%4};"
                 :: "l"(p), "f"(vals[0]), "f"(vals[1]), "f"(vals[2]), "f"(vals[3])
                 : "memory");
    asm volatile("red.global.add.v4.f32 [%0], {%1,%2,%3,%4};"
                 :: "l"(p + 4), "f"(vals[4]), "f"(vals[5]), "f"(vals[6]), "f"(vals[7])
                 : "memory");
}

// ---------------------------------------------------------------------------
// Load one d-slice's column of HT+4 h-rows (zero outside volume) and produce
// the HT 5-tap H-sums via an incremental sliding window.
// ---------------------------------------------------------------------------
__device__ __forceinline__ void load_hs(const float* __restrict__ in,
                                        int s, int h0, int w, float* hs)
{
    float v[HT + 4];
    if (s >= 0 && s < GRID3) {
        const float* slice = in + ((size_t)s << 16) + (size_t)w;
#pragma unroll
        for (int r = 0; r < HT + 4; r++) {
            int h = h0 - 2 + r;
            v[r] = (h >= 0 && h < GRID3) ? slice[(size_t)h << 8] : 0.f;
        }
    } else {
#pragma unroll
        for (int r = 0; r < HT + 4; r++) v[r] = 0.f;
    }
    hs[0] = ((v[0] + v[1]) + (v[2] + v[3])) + v[4];
#pragma unroll
    for (int i = 1; i < HT; i++)
        hs[i] = hs[i - 1] + (v[i + 4] - v[i - 1]);
}

// ---------------------------------------------------------------------------
// Fused H+D box blur, no shared memory. Thread = one w column within an
// (h-tile, d-segment) CTA. Peeled 4-slice warmup fills a 4-deep depth ring
// of H-sums; the fully-unrolled steady loop rotates the ring statically
// (no MOVs) and emits one output slice per step.
// ---------------------------------------------------------------------------
__global__ __launch_bounds__(256) void blur_hd_kernel(const float* __restrict__ in,
                                                      float* __restrict__ out)
{
    int w  = threadIdx.x;               // 0..255
    int h0 = blockIdx.x * HT;           // 32 tiles
    int d0 = blockIdx.y * DSEG;         // 32 segments

    float ring[4][HT];

    // Warmup: slices d0-2 .. d0+1
#pragma unroll
    for (int k = 0; k < 4; k++)
        load_hs(in, d0 - 2 + k, h0, w, ring[k]);

    // Steady: each step t loads slice d0+2+t and emits output slice d0+t.
#pragma unroll
    for (int t = 0; t < DSEG; t++) {
        float hs[HT];
        load_hs(in, d0 + 2 + t, h0, w, hs);
        float* o = out + ((size_t)(d0 + t) << 16) + ((size_t)h0 << 8) + (size_t)w;
#pragma unroll
        for (int i = 0; i < HT; i++) {
            o[(size_t)i << 8] =
                ((ring[0][i] + ring[1][i]) + (ring[2][i] + ring[3][i])) + hs[i];
            ring[t & 3][i] = hs[i];     // static after unroll: register rotation
        }
    }
}

// ---------------------------------------------------------------------------
// Launch: memset vol -> scatter+W (->vol) -> fused HD (vol -> d_out)
// All default-stream, graph-capturable, allocation-free.
// ---------------------------------------------------------------------------
extern "C" void kernel_launch(void* const* d_in, const int* in_sizes, int n_in,
                              void* d_out, int out_size)
{
    const float* feats  = (const float*)d_in[0];
    const int*   coords = (const int*)d_in[1];
    int n = in_sizes[0];
    float* out = (float*)d_out;

    float* vol = nullptr;
    cudaGetSymbolAddress((void**)&vol, g_vol);

    cudaMemsetAsync(vol, 0, (size_t)NVOX * sizeof(float));

    scatter_w_kernel<<<(n + 255) / 256, 256>>>(feats, coords, n);

    dim3 gridHD(GRID3 / HT, GRID3 / DSEG);
    blur_hd_kernel<<<gridHD, GRID3>>>(vol, out);
}